// round 17
// baseline (speedup 1.0000x reference)
#include <cuda_runtime.h>
#include <cstdint>

#define IN_DIM 128
#define OUT_DIM 128
#define MAX_NODES 50000
#define MAX_EDGES 800000
#define SCAN_BS 256
#define MAX_SCAN_BLOCKS ((MAX_NODES + SCAN_BS - 1) / SCAN_BS)   // 196

// Static scratch (zero-initialized at load; counters re-zeroed every launch)
__device__ int   g_degcnt[MAX_NODES];
__device__ int   g_rowcnt[MAX_NODES];
__device__ int   g_rowfill[MAX_NODES];
__device__ int   g_rowptr[MAX_NODES + 1];
__device__ int   g_pref[MAX_NODES];          // block-local inclusive prefix
__device__ int   g_bsum[MAX_SCAN_BLOCKS];    // per-block sums
__device__ int   g_boff[MAX_SCAN_BLOCKS];    // exclusive block offsets
__device__ int   g_cs[MAX_EDGES];
__device__ float g_dinv[MAX_NODES];
__device__ float g_h[(size_t)MAX_NODES * OUT_DIM];   // x @ W^T

// ---------------------------------------------------------------------------
// Histogram (scalar, one edge/thread); counters pre-zeroed by prior replay
// ---------------------------------------------------------------------------
__global__ void k_count(const int* __restrict__ row,
                        const int* __restrict__ col, int E) {
    int i = blockIdx.x * blockDim.x + threadIdx.x;
    if (i < E) {
        atomicAdd(&g_rowcnt[row[i]], 1);
        atomicAdd(&g_degcnt[col[i]], 1);
    }
}

// ---------------------------------------------------------------------------
// Scan phase 1: block-local inclusive scan of rowcnt -> g_pref, g_bsum
// ---------------------------------------------------------------------------
__global__ void __launch_bounds__(SCAN_BS) k_scan1(int n) {
    __shared__ int wsum[8];
    int i    = blockIdx.x * SCAN_BS + threadIdx.x;
    int lane = threadIdx.x & 31;
    int wid  = threadIdx.x >> 5;

    int v0 = (i < n) ? g_rowcnt[i] : 0;
    int v = v0;
#pragma unroll
    for (int o = 1; o < 32; o <<= 1) {
        int t = __shfl_up_sync(0xFFFFFFFFu, v, o);
        if (lane >= o) v += t;
    }
    if (lane == 31) wsum[wid] = v;
    __syncthreads();
    if (wid == 0 && lane < 8) {
        int wv = wsum[lane];
#pragma unroll
        for (int o = 1; o < 8; o <<= 1) {
            int t = __shfl_up_sync(0xFFu, wv, o);
            if (lane >= o) wv += t;
        }
        wsum[lane] = wv;
    }
    __syncthreads();
    int incl = v + (wid > 0 ? wsum[wid - 1] : 0);
    if (i < n) g_pref[i] = incl;
    if (threadIdx.x == SCAN_BS - 1) g_bsum[blockIdx.x] = incl;
}

// ---------------------------------------------------------------------------
// Scan phase 2: single block scans g_bsum -> exclusive offsets g_boff
// ---------------------------------------------------------------------------
__global__ void __launch_bounds__(SCAN_BS) k_scan2(int nb) {
    __shared__ int wsum[8];
    int t    = threadIdx.x;
    int lane = t & 31;
    int wid  = t >> 5;

    int v0 = (t < nb) ? g_bsum[t] : 0;
    int v = v0;
#pragma unroll
    for (int o = 1; o < 32; o <<= 1) {
        int s = __shfl_up_sync(0xFFFFFFFFu, v, o);
        if (lane >= o) v += s;
    }
    if (lane == 31) wsum[wid] = v;
    __syncthreads();
    if (wid == 0 && lane < 8) {
        int wv = wsum[lane];
#pragma unroll
        for (int o = 1; o < 8; o <<= 1) {
            int s = __shfl_up_sync(0xFFu, wv, o);
            if (lane >= o) wv += s;
        }
        wsum[lane] = wv;
    }
    __syncthreads();
    int incl = v + (wid > 0 ? wsum[wid - 1] : 0);
    if (t < nb) g_boff[t] = incl - v0;   // exclusive
}

// ---------------------------------------------------------------------------
// Scan phase 3: finalize rowptr/rowfill, dinv, re-zero counters
// ---------------------------------------------------------------------------
__global__ void __launch_bounds__(SCAN_BS) k_scan3(int n) {
    int i = blockIdx.x * SCAN_BS + threadIdx.x;
    if (i < n) {
        int off  = g_boff[blockIdx.x];
        int incl = off + g_pref[i];
        int cnt  = g_rowcnt[i];
        g_rowptr[i + 1] = incl;
        g_rowfill[i]    = incl - cnt;
        g_rowcnt[i]     = 0;
        g_dinv[i] = rsqrtf(1.0f + (float)g_degcnt[i]);
        g_degcnt[i] = 0;
    }
    if (i == 0) g_rowptr[0] = 0;
}

// ---------------------------------------------------------------------------
// Fill CSR (scalar): g_cs[atomicAdd(&g_rowfill[r],1)] = col
// ---------------------------------------------------------------------------
__global__ void k_fill(const int* __restrict__ row,
                       const int* __restrict__ col, int E) {
    int i = blockIdx.x * blockDim.x + threadIdx.x;
    if (i < E)
        g_cs[atomicAdd(&g_rowfill[row[i]], 1)] = col[i];
}

// ---------------------------------------------------------------------------
// GEMM (PROFILED SLOT idx 3): h[m][n] = sum_k x[m][k] * W[n][k]
// BM=64, BN=128, BK=8; 128 threads; 8x8 tile; 4 blocks/SM for latency hiding.
// Graph-independent (no dinv) — pure h write.
// ---------------------------------------------------------------------------
__global__ void __launch_bounds__(128, 4) k_gemm(const float* __restrict__ x,
                                                 const float* __restrict__ W,
                                                 int n_nodes) {
    __shared__ float As[8][64];    // As[k][m]
    __shared__ float Bs[8][128];   // Bs[k][n] = W[n][k]

    const int tid = threadIdx.x;
    const int bm  = blockIdx.x * 64;
    const int tx  = tid & 15;   // n: cols tx*8..+7
    const int ty  = tid >> 4;   // m: rows ty*8..+7 (0..7)

    float acc[8][8];
#pragma unroll
    for (int i = 0; i < 8; i++)
#pragma unroll
        for (int j = 0; j < 8; j++) acc[i][j] = 0.0f;

    // x tile: 64 rows x 8 k = 128 float4; 1/thread: row=tid>>1, chunk=(tid&1)*4
    const int xm  = tid >> 1;
    const int xk  = (tid & 1) * 4;
    const int m_ld = bm + xm;
    const bool m_ok = (m_ld < n_nodes);
    // W tile: 128 rows x 8 k = 256 float4; 2/thread: row=tid, chunks 0 and 4
    const int wn = tid;

    for (int kc = 0; kc < IN_DIM; kc += 8) {
        float4 xv = make_float4(0.f, 0.f, 0.f, 0.f);
        if (m_ok) xv = *(const float4*)(x + (size_t)m_ld * IN_DIM + kc + xk);
        float4 w0 = *(const float4*)(W + (size_t)wn * IN_DIM + kc);
        float4 w1 = *(const float4*)(W + (size_t)wn * IN_DIM + kc + 4);
        As[xk + 0][xm] = xv.x;
        As[xk + 1][xm] = xv.y;
        As[xk + 2][xm] = xv.z;
        As[xk + 3][xm] = xv.w;
        Bs[0][wn] = w0.x;
        Bs[1][wn] = w0.y;
        Bs[2][wn] = w0.z;
        Bs[3][wn] = w0.w;
        Bs[4][wn] = w1.x;
        Bs[5][wn] = w1.y;
        Bs[6][wn] = w1.z;
        Bs[7][wn] = w1.w;
        __syncthreads();

#pragma unroll
        for (int k = 0; k < 8; k++) {
            float4 a0 = ((const float4*)As[k])[ty * 2];
            float4 a1 = ((const float4*)As[k])[ty * 2 + 1];
            float4 b0 = ((const float4*)Bs[k])[tx * 2];
            float4 b1 = ((const float4*)Bs[k])[tx * 2 + 1];
            float av[8] = {a0.x, a0.y, a0.z, a0.w, a1.x, a1.y, a1.z, a1.w};
            float bv[8] = {b0.x, b0.y, b0.z, b0.w, b1.x, b1.y, b1.z, b1.w};
#pragma unroll
            for (int i = 0; i < 8; i++)
#pragma unroll
                for (int j = 0; j < 8; j++) acc[i][j] += av[i] * bv[j];
        }
        __syncthreads();
    }

#pragma unroll
    for (int i = 0; i < 8; i++) {
        int m = bm + ty * 8 + i;
        if (m >= n_nodes) continue;
        size_t base = (size_t)m * OUT_DIM + tx * 8;
        *(float4*)(g_h + base)     = make_float4(acc[i][0], acc[i][1], acc[i][2], acc[i][3]);
        *(float4*)(g_h + base + 4) = make_float4(acc[i][4], acc[i][5], acc[i][6], acc[i][7]);
    }
}

// ---------------------------------------------------------------------------
// Aggregate in h-space (same structure as xagg, measured 33us):
// out[i] = relu( dinv[i]^2 * h[i] + sum_{e in row i} dinv[i]*dinv[c] * h[c] )
// One warp per node, owner-computes, no atomics, write-once, fused relu.
// ---------------------------------------------------------------------------
__global__ void __launch_bounds__(256) k_hagg(float* __restrict__ out, int n) {
    int w    = (blockIdx.x * blockDim.x + threadIdx.x) >> 5;
    int lane = threadIdx.x & 31;
    if (w >= n) return;

    int s = g_rowptr[w];
    int e = g_rowptr[w + 1];
    float di = g_dinv[w];
    float di2 = di * di;

    float4 hs = *(const float4*)(g_h + (size_t)w * OUT_DIM + lane * 4);
    float4 acc = make_float4(di2 * hs.x, di2 * hs.y, di2 * hs.z, di2 * hs.w);

    int j = s;
    for (; j + 3 < e; j += 4) {
        int c0 = g_cs[j];
        int c1 = g_cs[j + 1];
        int c2 = g_cs[j + 2];
        int c3 = g_cs[j + 3];
        float w0 = di * g_dinv[c0];
        float w1 = di * g_dinv[c1];
        float w2 = di * g_dinv[c2];
        float w3 = di * g_dinv[c3];
        float4 h0 = *(const float4*)(g_h + (size_t)c0 * OUT_DIM + lane * 4);
        float4 h1 = *(const float4*)(g_h + (size_t)c1 * OUT_DIM + lane * 4);
        float4 h2 = *(const float4*)(g_h + (size_t)c2 * OUT_DIM + lane * 4);
        float4 h3 = *(const float4*)(g_h + (size_t)c3 * OUT_DIM + lane * 4);
        acc.x += w0 * h0.x + w1 * h1.x + w2 * h2.x + w3 * h3.x;
        acc.y += w0 * h0.y + w1 * h1.y + w2 * h2.y + w3 * h3.y;
        acc.z += w0 * h0.z + w1 * h1.z + w2 * h2.z + w3 * h3.z;
        acc.w += w0 * h0.w + w1 * h1.w + w2 * h2.w + w3 * h3.w;
    }
    for (; j < e; j++) {
        int c = g_cs[j];
        float wt = di * g_dinv[c];
        float4 hv = *(const float4*)(g_h + (size_t)c * OUT_DIM + lane * 4);
        acc.x += wt * hv.x;
        acc.y += wt * hv.y;
        acc.z += wt * hv.z;
        acc.w += wt * hv.w;
    }

    acc.x = fmaxf(acc.x, 0.f);
    acc.y = fmaxf(acc.y, 0.f);
    acc.z = fmaxf(acc.z, 0.f);
    acc.w = fmaxf(acc.w, 0.f);
    *(float4*)(out + (size_t)w * OUT_DIM + lane * 4) = acc;
}

// ---------------------------------------------------------------------------
extern "C" void kernel_launch(void* const* d_in, const int* in_sizes, int n_in,
                              void* d_out, int out_size) {
    const float* x  = (const float*)d_in[0];
    const float* W  = (const float*)d_in[1];
    const int*   ei = (const int*)d_in[2];   // int32 (JAX x64 disabled)
    float* out = (float*)d_out;

    const int n_nodes = in_sizes[0] / IN_DIM;
    const int E       = in_sizes[2] / 2;
    const int* row = ei;
    const int* col = ei + E;

    const int nb = (n_nodes + SCAN_BS - 1) / SCAN_BS;

    // gemm is graph-independent -> slot idx 3 (profiled)
    k_count<<<(E + 255) / 256, 256>>>(row, col, E);
    k_scan1<<<nb, SCAN_BS>>>(n_nodes);
    k_scan2<<<1, SCAN_BS>>>(nb);
    k_gemm <<<(n_nodes + 63) / 64, 128>>>(x, W, n_nodes);   // PROFILED
    k_scan3<<<nb, SCAN_BS>>>(n_nodes);
    k_fill <<<(E + 255) / 256, 256>>>(row, col, E);

    int warps_per_block = 256 / 32;
    int agg_blocks = (n_nodes + warps_per_block - 1) / warps_per_block;
    k_hagg <<<agg_blocks, 256>>>(out, n_nodes);
}